// round 12
// baseline (speedup 1.0000x reference)
#include <cuda_runtime.h>
#include <stdint.h>

// Hadamard on qubit TARGET=5 of a 24-qubit real fp32 statevector, batch 2.
// Pair partner at element-stride 2^18 => float4-stride 2^16.
// 2^23 float4s total, 2^22 pairs. Each thread handles FOUR pairs
// (8 independent LDG.128 front-batched, MLP=8), grid-split into four
// widely separated streams so every access stays perfectly coalesced.
// Streaming cache hints (.cs) since no byte is ever reused.
//
// Converged configuration: MLP=16 variant measured identical DRAM% (75.9)
// with occ 20.5% vs 48.5% — we are at the HBM read+write service ceiling
// (~6.0 TB/s of 8 TB/s spec on a 50/50 R/W stream), so MLP=8 is the
// sweet spot: same bandwidth, half the register pressure.

__global__ void __launch_bounds__(256) hadamard_q5_kernel(
    const float4* __restrict__ in, float4* __restrict__ out)
{
    const unsigned t = blockIdx.x * blockDim.x + threadIdx.x;  // [0, 2^20)
    const float s = 0.70710678118654752440f;
    const unsigned STEP = 1u << 16;

    // Four pair indices in four widely separated streams.
    const unsigned p0 = t;
    const unsigned p1 = t + (1u << 20);
    const unsigned p2 = t + (2u << 20);
    const unsigned p3 = t + (3u << 20);

    const unsigned a0 = ((p0 >> 16) << 17) + (p0 & 0xFFFFu);
    const unsigned b0 = ((p1 >> 16) << 17) + (p1 & 0xFFFFu);
    const unsigned c0 = ((p2 >> 16) << 17) + (p2 & 0xFFFFu);
    const unsigned d0 = ((p3 >> 16) << 17) + (p3 & 0xFFFFu);

    // Front-batch all eight loads (MLP=8), evict-first.
    const float4 xa = __ldcs(in + a0);
    const float4 xb = __ldcs(in + a0 + STEP);
    const float4 ya = __ldcs(in + b0);
    const float4 yb = __ldcs(in + b0 + STEP);
    const float4 za = __ldcs(in + c0);
    const float4 zb = __ldcs(in + c0 + STEP);
    const float4 wa = __ldcs(in + d0);
    const float4 wb = __ldcs(in + d0 + STEP);

    float4 u, v;
    u.x = (xa.x + xb.x) * s;  v.x = (xa.x - xb.x) * s;
    u.y = (xa.y + xb.y) * s;  v.y = (xa.y - xb.y) * s;
    u.z = (xa.z + xb.z) * s;  v.z = (xa.z - xb.z) * s;
    u.w = (xa.w + xb.w) * s;  v.w = (xa.w - xb.w) * s;
    __stcs(out + a0, u);
    __stcs(out + a0 + STEP, v);

    u.x = (ya.x + yb.x) * s;  v.x = (ya.x - yb.x) * s;
    u.y = (ya.y + yb.y) * s;  v.y = (ya.y - yb.y) * s;
    u.z = (ya.z + yb.z) * s;  v.z = (ya.z - yb.z) * s;
    u.w = (ya.w + yb.w) * s;  v.w = (ya.w - yb.w) * s;
    __stcs(out + b0, u);
    __stcs(out + b0 + STEP, v);

    u.x = (za.x + zb.x) * s;  v.x = (za.x - zb.x) * s;
    u.y = (za.y + zb.y) * s;  v.y = (za.y - zb.y) * s;
    u.z = (za.z + zb.z) * s;  v.z = (za.z - zb.z) * s;
    u.w = (za.w + zb.w) * s;  v.w = (za.w - zb.w) * s;
    __stcs(out + c0, u);
    __stcs(out + c0 + STEP, v);

    u.x = (wa.x + wb.x) * s;  v.x = (wa.x - wb.x) * s;
    u.y = (wa.y + wb.y) * s;  v.y = (wa.y - wb.y) * s;
    u.z = (wa.z + wb.z) * s;  v.z = (wa.z - wb.z) * s;
    u.w = (wa.w + wb.w) * s;  v.w = (wa.w - wb.w) * s;
    __stcs(out + d0, u);
    __stcs(out + d0 + STEP, v);
}

extern "C" void kernel_launch(void* const* d_in, const int* in_sizes, int n_in,
                              void* d_out, int out_size)
{
    const float4* in  = (const float4*)d_in[0];
    float4*       out = (float4*)d_out;

    // 2^22 pairs, 4 pairs/thread -> 2^20 threads -> 4096 blocks of 256
    const unsigned threads = 256;
    const unsigned blocks  = (1u << 20) / threads;  // 4096

    hadamard_q5_kernel<<<blocks, threads>>>(in, out);
}

// round 13
// speedup vs baseline: 1.0537x; 1.0537x over previous
#include <cuda_runtime.h>
#include <stdint.h>

// Hadamard on qubit TARGET=5 of a 24-qubit real fp32 statevector, batch 2.
// Pair partner at element-stride 2^18 => float4-stride 2^16.
// 2^23 float4s total, 2^22 pairs. Each thread handles FOUR pairs
// (8 independent LDG.128 front-batched, MLP=8), grid-split into four
// widely separated streams so every access stays perfectly coalesced.
// Streaming cache hints (.cs) since no byte is ever reused.
//
// Converged configuration. Evidence across the MLP sweep (2/4/8/16):
// DRAM% saturates at 75.9% (~6.0 TB/s) for MLP>=8 — the HBM 50/50
// read+write service ceiling. MLP=8 keeps regs at 48 / occ ~49%, which
// is the most clock-droop-tolerant point at ceiling bandwidth.

__global__ void __launch_bounds__(256) hadamard_q5_kernel(
    const float4* __restrict__ in, float4* __restrict__ out)
{
    const unsigned t = blockIdx.x * blockDim.x + threadIdx.x;  // [0, 2^20)
    const float s = 0.70710678118654752440f;
    const unsigned STEP = 1u << 16;

    // Four pair indices in four widely separated streams.
    const unsigned p0 = t;
    const unsigned p1 = t + (1u << 20);
    const unsigned p2 = t + (2u << 20);
    const unsigned p3 = t + (3u << 20);

    const unsigned a0 = ((p0 >> 16) << 17) + (p0 & 0xFFFFu);
    const unsigned b0 = ((p1 >> 16) << 17) + (p1 & 0xFFFFu);
    const unsigned c0 = ((p2 >> 16) << 17) + (p2 & 0xFFFFu);
    const unsigned d0 = ((p3 >> 16) << 17) + (p3 & 0xFFFFu);

    // Front-batch all eight loads (MLP=8), evict-first.
    const float4 xa = __ldcs(in + a0);
    const float4 xb = __ldcs(in + a0 + STEP);
    const float4 ya = __ldcs(in + b0);
    const float4 yb = __ldcs(in + b0 + STEP);
    const float4 za = __ldcs(in + c0);
    const float4 zb = __ldcs(in + c0 + STEP);
    const float4 wa = __ldcs(in + d0);
    const float4 wb = __ldcs(in + d0 + STEP);

    float4 u, v;
    u.x = (xa.x + xb.x) * s;  v.x = (xa.x - xb.x) * s;
    u.y = (xa.y + xb.y) * s;  v.y = (xa.y - xb.y) * s;
    u.z = (xa.z + xb.z) * s;  v.z = (xa.z - xb.z) * s;
    u.w = (xa.w + xb.w) * s;  v.w = (xa.w - xb.w) * s;
    __stcs(out + a0, u);
    __stcs(out + a0 + STEP, v);

    u.x = (ya.x + yb.x) * s;  v.x = (ya.x - yb.x) * s;
    u.y = (ya.y + yb.y) * s;  v.y = (ya.y - yb.y) * s;
    u.z = (ya.z + yb.z) * s;  v.z = (ya.z - yb.z) * s;
    u.w = (ya.w + yb.w) * s;  v.w = (ya.w - yb.w) * s;
    __stcs(out + b0, u);
    __stcs(out + b0 + STEP, v);

    u.x = (za.x + zb.x) * s;  v.x = (za.x - zb.x) * s;
    u.y = (za.y + zb.y) * s;  v.y = (za.y - zb.y) * s;
    u.z = (za.z + zb.z) * s;  v.z = (za.z - zb.z) * s;
    u.w = (za.w + zb.w) * s;  v.w = (za.w - zb.w) * s;
    __stcs(out + c0, u);
    __stcs(out + c0 + STEP, v);

    u.x = (wa.x + wb.x) * s;  v.x = (wa.x - wb.x) * s;
    u.y = (wa.y + wb.y) * s;  v.y = (wa.y - wb.y) * s;
    u.z = (wa.z + wb.z) * s;  v.z = (wa.z - wb.z) * s;
    u.w = (wa.w + wb.w) * s;  v.w = (wa.w - wb.w) * s;
    __stcs(out + d0, u);
    __stcs(out + d0 + STEP, v);
}

extern "C" void kernel_launch(void* const* d_in, const int* in_sizes, int n_in,
                              void* d_out, int out_size)
{
    const float4* in  = (const float4*)d_in[0];
    float4*       out = (float4*)d_out;

    // 2^22 pairs, 4 pairs/thread -> 2^20 threads -> 4096 blocks of 256
    const unsigned threads = 256;
    const unsigned blocks  = (1u << 20) / threads;  // 4096

    hadamard_q5_kernel<<<blocks, threads>>>(in, out);
}